// round 1
// baseline (speedup 1.0000x reference)
#include <cuda_runtime.h>

// Problem constants (shapes fixed by the problem definition)
#define D      64      // embedding dim
#define KCB    1024    // codebook size
#define KT     256     // codebook tile (codes per smem tile)
#define NTILES (KCB / KT)
#define TLEN   8192    // sequence length T
#define BLK    256     // threads per block (1 token per thread)

// Scratch: transposed codebook [d][k] and half-squared-norms (device globals:
// no allocation allowed in kernel_launch)
__device__ float g_cbT[D * KCB];
__device__ float g_h[KCB];

// ---------------------------------------------------------------------------
// Prep: transpose codebook so 4 consecutive codes are contiguous per dim,
// and compute h[k] = 0.5 * ||e_k||^2.
// argmin_k ( ||x||^2 - 2 x.e_k + ||e_k||^2 )  ==  argmax_k ( x.e_k - h[k] )
// ---------------------------------------------------------------------------
__global__ void vq_prep(const float* __restrict__ cb) {
    int k = blockIdx.x * blockDim.x + threadIdx.x;
    if (k >= KCB) return;
    float hsum = 0.0f;
#pragma unroll
    for (int d = 0; d < D; d++) {
        float v = cb[k * D + d];
        g_cbT[d * KCB + k] = v;
        hsum = fmaf(v, v, hsum);
    }
    g_h[k] = 0.5f * hsum;
}

// ---------------------------------------------------------------------------
// Main: each thread owns one token. x[64] lives in registers; codebook tiles
// are staged in smem transposed so the inner loop is
//   per d, per 4 codes:  1x LDS.128 (warp-uniform broadcast) + 4x FFMA.
// Score tracking keeps the earliest index on exact ties (matches argmin).
// ---------------------------------------------------------------------------
__global__ void __launch_bounds__(BLK)
vq_main(const float* __restrict__ xin,
        const float* __restrict__ cb,
        float* __restrict__ out,
        float* __restrict__ outidx) {
    __shared__ __align__(16) float sE[D * KT];
    __shared__ __align__(16) float sH[KT];

    const int n  = blockIdx.x * BLK + threadIdx.x;  // global token id
    const int b  = n / TLEN;
    const int tl = n % TLEN;

    // Load this token's vector: input layout (B, D, T) -> stride T per dim.
    // Consecutive threads hit consecutive tl -> fully coalesced per d.
    const float* xp = xin + (size_t)b * D * TLEN + tl;
    float x[D];
#pragma unroll
    for (int d = 0; d < D; d++) x[d] = xp[(size_t)d * TLEN];

    float best = -3.4e38f;
    int   bidx = 0;

    for (int tile = 0; tile < NTILES; tile++) {
        __syncthreads();  // previous tile fully consumed
        // Cooperative tile load (L2-resident source, coalesced rows)
        for (int i = threadIdx.x; i < D * KT; i += BLK) {
            int d = i >> 8;          // i / KT  (KT == 256)
            int k = i & (KT - 1);    // i % KT
            sE[i] = g_cbT[d * KCB + tile * KT + k];
        }
        for (int i = threadIdx.x; i < KT; i += BLK)
            sH[i] = g_h[tile * KT + i];
        __syncthreads();

        for (int k = 0; k < KT; k += 4) {
            float a0 = 0.f, a1 = 0.f, a2 = 0.f, a3 = 0.f;
#pragma unroll
            for (int d = 0; d < D; d++) {
                float4 e = *reinterpret_cast<const float4*>(&sE[d * KT + k]);
                float xd = x[d];
                a0 = fmaf(xd, e.x, a0);
                a1 = fmaf(xd, e.y, a1);
                a2 = fmaf(xd, e.z, a2);
                a3 = fmaf(xd, e.w, a3);
            }
            float4 hh = *reinterpret_cast<const float4*>(&sH[k]);
            float s0 = a0 - hh.x;
            float s1 = a1 - hh.y;
            float s2 = a2 - hh.z;
            float s3 = a3 - hh.w;
            int kb = tile * KT + k;
            if (s0 > best) { best = s0; bidx = kb;     }
            if (s1 > best) { best = s1; bidx = kb + 1; }
            if (s2 > best) { best = s2; bidx = kb + 2; }
            if (s3 > best) { best = s3; bidx = kb + 3; }
        }
    }

    // Epilogue: gather winning codebook row (vectorized, L2 hit) and write
    // back in (B, D, T) layout -> strided but coalesced across the warp.
    const float4* row = reinterpret_cast<const float4*>(cb + (size_t)bidx * D);
    float* op = out + (size_t)b * D * TLEN + tl;
#pragma unroll
    for (int q = 0; q < D / 4; q++) {
        float4 v = row[q];
        op[(size_t)(4 * q + 0) * TLEN] = v.x;
        op[(size_t)(4 * q + 1) * TLEN] = v.y;
        op[(size_t)(4 * q + 2) * TLEN] = v.z;
        op[(size_t)(4 * q + 3) * TLEN] = v.w;
    }
    outidx[n] = (float)bidx;  // indices 0..1023 exactly representable
}

// ---------------------------------------------------------------------------
extern "C" void kernel_launch(void* const* d_in, const int* in_sizes, int n_in,
                              void* d_out, int out_size) {
    const float* x  = (const float*)d_in[0];   // input (16, 64, 8192)
    const float* cb = (const float*)d_in[1];   // codebook (1024, 64)
    float* out = (float*)d_out;

    const int N = in_sizes[0] / D;             // total tokens = B*T
    float* oidx = out + (size_t)N * D;         // indices appended after values

    vq_prep<<<(KCB + 255) / 256, 256>>>(cb);
    vq_main<<<N / BLK, BLK>>>(x, cb, out, oidx);
}

// round 2
// speedup vs baseline: 1.6135x; 1.6135x over previous
#include <cuda_runtime.h>
#include <cstdint>

#define D      64      // embedding dim
#define KCB    1024    // codebook size
#define TLEN   8192    // sequence length T
#define BLK    256     // threads per block
#define TOK    128     // tokens per block
#define KT2    128     // codes per smem tile
#define NTILE  (KCB / KT2)
#define MT     8       // tokens per thread (4 packed pairs)
#define NT     4       // codes per thread per sweep
#define CI_N   16      // code-group threads  (16*4  = 64 codes / sweep)
#define TI_N   16      // token-group threads (16*8  = 128 tokens)
#define NSWEEP (KT2 / (CI_N * NT))   // 2 sweeps per tile

// Scratch (device globals: no allocation allowed in kernel_launch)
__device__ float g_cbT[D * KCB];   // transposed codebook [d][k]
__device__ float g_h[KCB];         // 0.5 * ||e_k||^2

// ---- packed f32x2 helpers (sm_103a) ---------------------------------------
__device__ __forceinline__ unsigned long long pack2dup(float a) {
    unsigned long long r;
    asm("mov.b64 %0, {%1, %1};" : "=l"(r) : "f"(a));
    return r;
}
__device__ __forceinline__ unsigned long long fma2(unsigned long long a,
                                                   unsigned long long b,
                                                   unsigned long long c) {
    unsigned long long r;
    asm("fma.rn.f32x2 %0, %1, %2, %3;" : "=l"(r) : "l"(a), "l"(b), "l"(c));
    return r;
}
__device__ __forceinline__ float2 unpack2(unsigned long long v) {
    float2 f;
    asm("mov.b64 {%0, %1}, %2;" : "=f"(f.x), "=f"(f.y) : "l"(v));
    return f;
}

// ---------------------------------------------------------------------------
// Prep: transpose codebook + precompute h[k] = 0.5*||e_k||^2.
// argmin_k(||x||^2 - 2 x.e + ||e||^2) == argmax_k(x.e_k - h[k])
// ---------------------------------------------------------------------------
__global__ void vq_prep(const float* __restrict__ cb) {
    int k = blockIdx.x * blockDim.x + threadIdx.x;
    if (k >= KCB) return;
    float hsum = 0.0f;
#pragma unroll
    for (int d = 0; d < D; d++) {
        float v = cb[k * D + d];
        g_cbT[d * KCB + k] = v;
        hsum = fmaf(v, v, hsum);
    }
    g_h[k] = 0.5f * hsum;
}

// ---------------------------------------------------------------------------
// Main: block owns 128 tokens. x staged transposed in smem [d][t]; codebook
// staged in tiles of 128 codes [d][k]. Each thread computes an 8-token x
// 4-code micro-tile with packed fma.rn.f32x2 (token pairs come pre-packed
// straight out of LDS.128).
// ---------------------------------------------------------------------------
__global__ void __launch_bounds__(BLK)
vq_main(const float* __restrict__ xin,
        const float* __restrict__ cb,
        float* __restrict__ out,
        float* __restrict__ outidx) {
    __shared__ __align__(16) float sX[D][TOK];   // 32 KB
    __shared__ __align__(16) float sE[D][KT2];   // 32 KB
    __shared__ __align__(16) float sH[KT2];
    __shared__ int sIdx[TOK];

    const int tid = threadIdx.x;
    const int n0  = blockIdx.x * TOK;        // first token of block
    const int b   = n0 / TLEN;
    const int t0  = n0 % TLEN;               // TOK divides TLEN -> same b for block

    // Stage token vectors transposed: (B, D, T) layout -> coalesced over t.
    const float* xbase = xin + (size_t)b * D * TLEN + t0;
    for (int i = tid; i < D * TOK; i += BLK) {
        int d = i >> 7;          // / TOK
        int t = i & (TOK - 1);
        sX[d][t] = xbase[(size_t)d * TLEN + t];
    }

    const int ci = tid & (CI_N - 1);   // code group
    const int ti = tid >> 4;           // token group

    float best[MT];
    int   bidx[MT];
#pragma unroll
    for (int m = 0; m < MT; m++) { best[m] = -3.4e38f; bidx[m] = 0; }

    for (int tile = 0; tile < NTILE; tile++) {
        __syncthreads();   // sX ready (tile 0) / previous tile consumed
        for (int i = tid; i < D * KT2; i += BLK) {
            int d = i >> 7;
            int k = i & (KT2 - 1);
            sE[d][k] = g_cbT[d * KCB + tile * KT2 + k];
        }
        for (int i = tid; i < KT2; i += BLK)
            sH[i] = g_h[tile * KT2 + i];
        __syncthreads();

        for (int sweep = 0; sweep < NSWEEP; sweep++) {
            const int kloc = sweep * (CI_N * NT) + ci * NT;

            unsigned long long acc[4][NT];   // [token pair][code]
#pragma unroll
            for (int p = 0; p < 4; p++)
#pragma unroll
                for (int c = 0; c < NT; c++) acc[p][c] = 0ull;

#pragma unroll 8
            for (int d = 0; d < D; d++) {
                // 8 tokens = 4 pre-packed f32x2 pairs (two LDS.128)
                ulonglong2 xu0 = *reinterpret_cast<const ulonglong2*>(&sX[d][ti * MT]);
                ulonglong2 xu1 = *reinterpret_cast<const ulonglong2*>(&sX[d][ti * MT + 4]);
                // 4 codes (one LDS.128), dup-packed per code
                float4 ev = *reinterpret_cast<const float4*>(&sE[d][kloc]);
                unsigned long long e0 = pack2dup(ev.x);
                unsigned long long e1 = pack2dup(ev.y);
                unsigned long long e2 = pack2dup(ev.z);
                unsigned long long e3 = pack2dup(ev.w);

                acc[0][0] = fma2(xu0.x, e0, acc[0][0]);
                acc[0][1] = fma2(xu0.x, e1, acc[0][1]);
                acc[0][2] = fma2(xu0.x, e2, acc[0][2]);
                acc[0][3] = fma2(xu0.x, e3, acc[0][3]);
                acc[1][0] = fma2(xu0.y, e0, acc[1][0]);
                acc[1][1] = fma2(xu0.y, e1, acc[1][1]);
                acc[1][2] = fma2(xu0.y, e2, acc[1][2]);
                acc[1][3] = fma2(xu0.y, e3, acc[1][3]);
                acc[2][0] = fma2(xu1.x, e0, acc[2][0]);
                acc[2][1] = fma2(xu1.x, e1, acc[2][1]);
                acc[2][2] = fma2(xu1.x, e2, acc[2][2]);
                acc[2][3] = fma2(xu1.x, e3, acc[2][3]);
                acc[3][0] = fma2(xu1.y, e0, acc[3][0]);
                acc[3][1] = fma2(xu1.y, e1, acc[3][1]);
                acc[3][2] = fma2(xu1.y, e2, acc[3][2]);
                acc[3][3] = fma2(xu1.y, e3, acc[3][3]);
            }

            // score = dot - h; track running argmax per token.
            float4 hh = *reinterpret_cast<const float4*>(&sH[kloc]);
            const float hv[NT] = {hh.x, hh.y, hh.z, hh.w};
            const int kg0 = tile * KT2 + kloc;
#pragma unroll
            for (int c = 0; c < NT; c++) {
                const int kg = kg0 + c;
#pragma unroll
                for (int p = 0; p < 4; p++) {
                    float2 s = unpack2(acc[p][c]);
                    float s0 = s.x - hv[c];
                    float s1 = s.y - hv[c];
                    int m0 = 2 * p, m1 = 2 * p + 1;
                    if (s0 > best[m0]) { best[m0] = s0; bidx[m0] = kg; }
                    if (s1 > best[m1]) { best[m1] = s1; bidx[m1] = kg; }
                }
            }
        }
    }

    // Reduce argmax across the 16 threads (ci lanes) sharing each token group.
    // Tie-break on smaller index to match argmin's first-occurrence rule.
#pragma unroll
    for (int m = 0; m < MT; m++) {
        float bv = best[m];
        int   bi = bidx[m];
#pragma unroll
        for (int off = 8; off > 0; off >>= 1) {
            float ov = __shfl_xor_sync(0xffffffffu, bv, off);
            int   oi = __shfl_xor_sync(0xffffffffu, bi, off);
            if (ov > bv || (ov == bv && oi < bi)) { bv = ov; bi = oi; }
        }
        if (ci == 0) sIdx[ti * MT + m] = bi;
    }
    __syncthreads();

    // Epilogue: gather winning rows + write (B, D, T) coalesced over t.
    float* obase = out + (size_t)b * D * TLEN + t0;
    for (int i = tid; i < D * TOK; i += BLK) {
        int d = i >> 7;
        int t = i & (TOK - 1);
        obase[(size_t)d * TLEN + t] = cb[sIdx[t] * D + d];
    }
    for (int i = tid; i < TOK; i += BLK)
        outidx[n0 + i] = (float)sIdx[i];
}

// ---------------------------------------------------------------------------
extern "C" void kernel_launch(void* const* d_in, const int* in_sizes, int n_in,
                              void* d_out, int out_size) {
    const float* x  = (const float*)d_in[0];   // (16, 64, 8192)
    const float* cb = (const float*)d_in[1];   // (1024, 64)
    float* out = (float*)d_out;

    const int N = in_sizes[0] / D;             // total tokens
    float* oidx = out + (size_t)N * D;         // indices after quantized values

    vq_prep<<<(KCB + 255) / 256, 256>>>(cb);
    vq_main<<<N / TOK, BLK>>>(x, cb, out, oidx);
}

// round 4
// speedup vs baseline: 2.2759x; 1.4105x over previous
#include <cuda_runtime.h>
#include <cuda_bf16.h>
#include <cstdint>

#define D       64
#define KCB     1024
#define TLEN    8192
#define MTOK    128       // tokens per CTA
#define THREADS 256       // 8 warps, 16 tokens per warp
#define CHUNK   256       // codes per chunk
#define NCHUNK  4
#define TAU     3e-3f
#define NTOKMAX 131072

// ---- dynamic smem layout (bytes) ----
#define OFF_XHI  0                 // 128 tokens x 128B rows (bf16 hi), SW128
#define OFF_XLO  16384
#define OFF_B    32768             // 2 bufs x (hi 32KB + lo 32KB)
#define OFF_H    163840            // float[1024]
#define OFF_IDX  167936            // int[128]
#define SMEM_TOTAL 168448

// ---- global scratch (no allocs allowed in kernel_launch) ----
__device__ __align__(16) __nv_bfloat16 g_cbHi[KCB * D];  // [k][d]
__device__ __align__(16) __nv_bfloat16 g_cbLo[KCB * D];
__device__ float g_h[KCB];
__device__ int   g_flag[NTOKMAX];

// ============================ PTX helpers ===================================
__device__ __forceinline__ uint32_t smem_u32(const void* p) {
    uint32_t a;
    asm("{ .reg .u64 t; cvta.to.shared.u64 t, %1; cvt.u32.u64 %0, t; }"
        : "=r"(a) : "l"(p));
    return a;
}
__device__ __forceinline__ void ldsm_x4(uint32_t r[4], uint32_t addr) {
    asm volatile("ldmatrix.sync.aligned.m8n8.x4.shared.b16 {%0,%1,%2,%3}, [%4];"
                 : "=r"(r[0]), "=r"(r[1]), "=r"(r[2]), "=r"(r[3]) : "r"(addr));
}
__device__ __forceinline__ void mma_bf16(float c[4], const uint32_t a[4],
                                         uint32_t b0, uint32_t b1) {
    asm volatile(
        "mma.sync.aligned.m16n8k16.row.col.f32.bf16.bf16.f32 "
        "{%0,%1,%2,%3}, {%4,%5,%6,%7}, {%8,%9}, {%0,%1,%2,%3};"
        : "+f"(c[0]), "+f"(c[1]), "+f"(c[2]), "+f"(c[3])
        : "r"(a[0]), "r"(a[1]), "r"(a[2]), "r"(a[3]), "r"(b0), "r"(b1));
}
__device__ __forceinline__ void cp16(uint32_t dst, const void* src) {
    asm volatile("cp.async.ca.shared.global [%0], [%1], 16;"
                 :: "r"(dst), "l"(src) : "memory");
}
__device__ __forceinline__ void cp_commit() {
    asm volatile("cp.async.commit_group;" ::: "memory");
}
template <int N> __device__ __forceinline__ void cp_wait() {
    asm volatile("cp.async.wait_group %0;" :: "n"(N) : "memory");
}
__device__ __forceinline__ uint32_t sw128(uint32_t off) {
    return off ^ ((off >> 3) & 0x70);
}

// ============================ prep ==========================================
// Codebook -> bf16 hi/lo (row-major [k][d]) + h[k] = 0.5*||e_k||^2 (exact fp32).
__global__ void vq_prep(const float* __restrict__ cb) {
    int k = blockIdx.x * blockDim.x + threadIdx.x;
    if (k >= KCB) return;
    float hsum = 0.0f;
#pragma unroll
    for (int d = 0; d < D; d++) {
        float v = cb[k * D + d];
        __nv_bfloat16 hi = __float2bfloat16(v);
        __nv_bfloat16 lo = __float2bfloat16(v - __bfloat162float(hi));
        g_cbHi[k * D + d] = hi;
        g_cbLo[k * D + d] = lo;
        hsum = fmaf(v, v, hsum);
    }
    g_h[k] = 0.5f * hsum;
}

// ============================ main ==========================================
__device__ __forceinline__ void issueB(uint32_t smbase, int buf, int chunk, int tid) {
    // 256 codes x 128B (hi) and (lo), SW128-swizzled rows, via cp.async 16B.
    uint32_t dH = smbase + OFF_B + buf * 65536;
    uint32_t dL = dH + 32768;
    const char* sH = reinterpret_cast<const char*>(g_cbHi) + (size_t)chunk * CHUNK * D * 2;
    const char* sL = reinterpret_cast<const char*>(g_cbLo) + (size_t)chunk * CHUNK * D * 2;
#pragma unroll
    for (int i = tid; i < 2048; i += THREADS) {
        int code = i >> 3, q = i & 7;
        uint32_t sw = sw128((uint32_t)(code * 128 + q * 16));
        cp16(dH + sw, sH + i * 16);
        cp16(dL + sw, sL + i * 16);
    }
}

__device__ __forceinline__ void upd(float& b, float& s, int& bi, float v, int k) {
    s = fmaxf(s, fminf(v, b));      // running second-best
    if (v > b) { b = v; bi = k; }   // strict > keeps first occurrence
}

__global__ void __launch_bounds__(THREADS, 1)
vq_mma(const float* __restrict__ xin, const float* __restrict__ cb,
       float* __restrict__ out, float* __restrict__ outidx) {
    extern __shared__ __align__(1024) char sm[];
    const uint32_t smbase = smem_u32(sm);
    const int tid  = threadIdx.x;
    const int lane = tid & 31, warp = tid >> 5;

    const int n0 = blockIdx.x * MTOK;
    const int b  = n0 >> 13;            // / TLEN
    const int t0 = n0 & (TLEN - 1);

    // Kick off codebook chunks 0,1 first so they overlap X staging.
    issueB(smbase, 0, 0, tid); cp_commit();
    issueB(smbase, 1, 1, tid); cp_commit();

    // Stage X as bf16 hi/lo, SW128 rows of 128B (row = token).
    const float* xbase = xin + (size_t)b * D * TLEN + t0;
    for (int i = tid; i < MTOK * D; i += THREADS) {
        int d = i >> 7, m = i & 127;    // coalesced over m
        float v = xbase[(size_t)d * TLEN + m];
        __nv_bfloat16 hi = __float2bfloat16(v);
        __nv_bfloat16 lo = __float2bfloat16(v - __bfloat162float(hi));
        uint32_t sw = sw128((uint32_t)(m * 128 + d * 2));
        *reinterpret_cast<__nv_bfloat16*>(sm + OFF_XHI + sw) = hi;
        *reinterpret_cast<__nv_bfloat16*>(sm + OFF_XLO + sw) = lo;
    }
    float* sH = reinterpret_cast<float*>(sm + OFF_H);
    for (int i = tid; i < KCB; i += THREADS) sH[i] = g_h[i];
    __syncthreads();    // X + h visible to all warps

    // A fragments (held in registers for the whole kernel).
    // ldmatrix.x4: row = lane&15 (token in warp tile), dim half = lane>>4.
    uint32_t aHi[4][4], aLo[4][4];
    {
        int arow = warp * 16 + (lane & 15);
        int adim = (lane >> 4) * 16;            // byte offset of 8-dim half
#pragma unroll
        for (int s = 0; s < 4; s++) {
            uint32_t off = (uint32_t)(arow * 128 + s * 32 + adim);
            uint32_t sw = sw128(off);
            ldsm_x4(aHi[s], smbase + OFF_XHI + sw);
            ldsm_x4(aLo[s], smbase + OFF_XLO + sw);
        }
    }

    // B-fragment per-thread addressing (16 codes x 16 dims per ldmatrix.x4):
    // code_local = (lane&7) + ((lane>>4)<<3), dim half = (lane>>3)&1.
    const uint32_t browoff = (uint32_t)(((lane & 7) + ((lane >> 4) << 3)) * 128);
    const uint32_t bxor = (uint32_t)((lane & 7) << 4);
    uint32_t bdim[4];
#pragma unroll
    for (int s = 0; s < 4; s++)
        bdim[s] = ((uint32_t)(s * 32 + ((lane >> 3) & 1) * 16)) ^ bxor;

    float best[2] = {-3.4e38f, -3.4e38f}, sec[2] = {-3.4e38f, -3.4e38f};
    int   bidx[2] = {0, 0};
    const int hcol = (lane & 3) * 2;

    for (int c = 0; c < NCHUNK; c++) {
        if (c == NCHUNK - 1) cp_wait<0>(); else cp_wait<1>();
        __syncthreads();                 // buf (c&1) ready for everyone
        const uint32_t bufHi = smbase + OFF_B + (c & 1) * 65536;
        const uint32_t bufLo = bufHi + 32768;

#pragma unroll 4
        for (int ns = 0; ns < CHUNK / 16; ns++) {
            const uint32_t ro = browoff + (uint32_t)(ns * 16 * 128);
            float a0h[4] = {0, 0, 0, 0}, a0x[4] = {0, 0, 0, 0};  // ntile 0
            float a1h[4] = {0, 0, 0, 0}, a1x[4] = {0, 0, 0, 0};  // ntile 1
#pragma unroll
            for (int s = 0; s < 4; s++) {
                uint32_t rh[4], rl[4];
                ldsm_x4(rh, bufHi + ro + bdim[s]);
                ldsm_x4(rl, bufLo + ro + bdim[s]);
                mma_bf16(a0h, aHi[s], rh[0], rh[1]);   // hi*hi
                mma_bf16(a1h, aHi[s], rh[2], rh[3]);
                mma_bf16(a0x, aHi[s], rl[0], rl[1]);   // hi*lo
                mma_bf16(a1x, aHi[s], rl[2], rl[3]);
                mma_bf16(a0x, aLo[s], rh[0], rh[1]);   // lo*hi
                mma_bf16(a1x, aLo[s], rh[2], rh[3]);
            }
            const int kb = c * CHUNK + ns * 16;
            float2 h0 = *reinterpret_cast<const float2*>(&sH[kb + hcol]);
            float2 h1 = *reinterpret_cast<const float2*>(&sH[kb + 8 + hcol]);
            // slot 0 = token row r (c0,c1); slot 1 = row r+8 (c2,c3).
            upd(best[0], sec[0], bidx[0], (a0h[0] + a0x[0]) - h0.x, kb + hcol);
            upd(best[0], sec[0], bidx[0], (a0h[1] + a0x[1]) - h0.y, kb + hcol + 1);
            upd(best[0], sec[0], bidx[0], (a1h[0] + a1x[0]) - h1.x, kb + 8 + hcol);
            upd(best[0], sec[0], bidx[0], (a1h[1] + a1x[1]) - h1.y, kb + 8 + hcol + 1);
            upd(best[1], sec[1], bidx[1], (a0h[2] + a0x[2]) - h0.x, kb + hcol);
            upd(best[1], sec[1], bidx[1], (a0h[3] + a0x[3]) - h0.y, kb + hcol + 1);
            upd(best[1], sec[1], bidx[1], (a1h[2] + a1x[2]) - h1.x, kb + 8 + hcol);
            upd(best[1], sec[1], bidx[1], (a1h[3] + a1x[3]) - h1.y, kb + 8 + hcol + 1);
        }
        __syncthreads();                 // everyone done reading buf (c&1)
        if (c + 2 < NCHUNK) { issueB(smbase, c & 1, c + 2, tid); cp_commit(); }
    }

    // Reduce across the 4 lanes (lane&3) sharing each token row.
    int* sIdx = reinterpret_cast<int*>(sm + OFF_IDX);
#pragma unroll
    for (int slot = 0; slot < 2; slot++) {
        float bv = best[slot], sv = sec[slot];
        int bi = bidx[slot];
#pragma unroll
        for (int off = 1; off <= 2; off <<= 1) {
            float ob = __shfl_xor_sync(0xffffffffu, bv, off);
            float os = __shfl_xor_sync(0xffffffffu, sv, off);
            int   oi = __shfl_xor_sync(0xffffffffu, bi, off);
            sv = fmaxf(fmaxf(sv, os), fminf(bv, ob));
            bool t = (ob > bv) || (ob == bv && oi < bi);  // tie -> smaller idx
            bv = t ? ob : bv;
            bi = t ? oi : bi;
        }
        if ((lane & 3) == 0) {
            int m = warp * 16 + (lane >> 2) + slot * 8;
            sIdx[m] = bi;
            g_flag[n0 + m] = (bv - sv < TAU) ? 1 : 0;
            outidx[n0 + m] = (float)bi;
        }
    }
    __syncthreads();

    // Gather winning codebook rows; coalesced over tokens per dim.
    float* obase = out + (size_t)b * D * TLEN + t0;
    for (int i = tid; i < MTOK * D; i += THREADS) {
        int d = i >> 7, mm = i & 127;
        obase[(size_t)d * TLEN + mm] = cb[sIdx[mm] * D + d];
    }
}

// ============================ exact refine ==================================
// One warp per flagged token; exact fp32 fmaf chain (matched reference in R1/R2).
__global__ void __launch_bounds__(256) vq_refine(const float* __restrict__ xin,
                                                 const float* __restrict__ cb,
                                                 float* __restrict__ out,
                                                 float* __restrict__ outidx,
                                                 int Ntok) {
    __shared__ float sx[8][D];
    const int wid = threadIdx.x >> 5, lid = threadIdx.x & 31;
    const int n = blockIdx.x * 8 + wid;
    if (n >= Ntok) return;
    if (g_flag[n] == 0) return;

    const int b = n / TLEN, t = n % TLEN;
    const float* xp = xin + (size_t)b * D * TLEN + t;
    sx[wid][lid]      = xp[(size_t)lid * TLEN];
    sx[wid][lid + 32] = xp[(size_t)(lid + 32) * TLEN];
    __syncwarp();

    float best = -3.4e38f;
    int   bi = 0;
    for (int kk = 0; kk < KCB / 32; kk++) {
        int k = kk * 32 + lid;
        const float4* row = reinterpret_cast<const float4*>(cb + (size_t)k * D);
        float dot = 0.0f;
#pragma unroll
        for (int q = 0; q < 16; q++) {
            float4 e = row[q];
            dot = fmaf(sx[wid][4 * q + 0], e.x, dot);
            dot = fmaf(sx[wid][4 * q + 1], e.y, dot);
            dot = fmaf(sx[wid][4 * q + 2], e.z, dot);
            dot = fmaf(sx[wid][4 * q + 3], e.w, dot);
        }
        float s = dot - g_h[k];
        if (s > best) { best = s; bi = k; }
    }
#pragma unroll
    for (int off = 16; off; off >>= 1) {   // tie -> smaller index
        float ov = __shfl_xor_sync(0xffffffffu, best, off);
        int   oi = __shfl_xor_sync(0xffffffffu, bi, off);
        if (ov > best || (ov == best && oi < bi)) { best = ov; bi = oi; }
    }
    bi = __shfl_sync(0xffffffffu, bi, 0);

    float* op = out + (size_t)b * D * TLEN + t;
    op[(size_t)lid * TLEN]        = cb[bi * D + lid];
    op[(size_t)(lid + 32) * TLEN] = cb[bi * D + lid + 32];
    if (lid == 0) outidx[n] = (float)bi;
}

// ============================ launch ========================================
extern "C" void kernel_launch(void* const* d_in, const int* in_sizes, int n_in,
                              void* d_out, int out_size) {
    const float* x  = (const float*)d_in[0];   // (16, 64, 8192)
    const float* cb = (const float*)d_in[1];   // (1024, 64)
    float* out = (float*)d_out;

    const int N = in_sizes[0] / D;
    float* oidx = out + (size_t)N * D;

    cudaFuncSetAttribute(vq_mma, cudaFuncAttributeMaxDynamicSharedMemorySize,
                         SMEM_TOTAL);

    vq_prep<<<KCB / 256, 256>>>(cb);
    vq_mma<<<N / MTOK, THREADS, SMEM_TOTAL>>>(x, cb, out, oidx);
    vq_refine<<<N / 8, 256>>>(x, cb, out, oidx, N);
}